// round 11
// baseline (speedup 1.0000x reference)
#include <cuda_runtime.h>

// Problem constants
#define N_LEN   131072
#define B_ROWS  256

// Tiling: each WARP owns one 256-position tile of a row-pair, fully autonomously.
#define TPB     128
#define NWARP   4
#define WTILE   256                    // positions per warp tile
#define EPT     8                      // positions per lane
#define W_IN    (WTILE + 32)           // 288 x-pairs incl 32-halo
#define W_PAD   ((W_IN / 8) * 9)       // 324 u64 slots per warp (pad-9-per-8)

typedef unsigned long long u64;

__device__ __forceinline__ u64 pack2(float a, float b) {
    u64 r; asm("mov.b64 %0,{%1,%2};" : "=l"(r) : "f"(a), "f"(b)); return r;
}
__device__ __forceinline__ void unpack2(u64 v, float& a, float& b) {
    asm("mov.b64 {%0,%1},%2;" : "=f"(a), "=f"(b) : "l"(v));
}
__device__ __forceinline__ u64 fma2(u64 a, u64 b, u64 c) {
    u64 d; asm("fma.rn.f32x2 %0,%1,%2,%3;" : "=l"(d) : "l"(a), "l"(b), "l"(c)); return d;
}
__device__ __forceinline__ u64 mul2(u64 a, u64 b) {
    u64 d; asm("mul.rn.f32x2 %0,%1,%2;" : "=l"(d) : "l"(a), "l"(b)); return d;
}
__device__ __forceinline__ u64 add2(u64 a, u64 b) {
    u64 d; asm("add.rn.f32x2 %0,%1,%2;" : "=l"(d) : "l"(a), "l"(b)); return d;
}

// pad-9-per-8 swizzle on u64 slots: stride-8 lane patterns -> addr stride 9 (odd) -> CF
__device__ __forceinline__ int sw(int k) { return (k >> 3) * 9 + (k & 7); }

__global__ void __launch_bounds__(TPB, 5) fir2(const float* __restrict__ x,
                                               const float* __restrict__ h,
                                               float* __restrict__ y) {
    __shared__ u64 sX[NWARP][W_PAD];   // per-warp x window; reused for y staging
    __shared__ u64 sHv[NWARP][16];     // per-warp tile-boundary v halo

    const int lane = threadIdx.x & 31;
    const int wid  = threadIdx.x >> 5;
    const int pair = blockIdx.y;
    const int c0   = blockIdx.x * (NWARP * WTILE) + wid * WTILE;  // warp tile base
    const float* __restrict__ x0 = x + (size_t)(2 * pair) * N_LEN;
    const float* __restrict__ x1 = x0 + N_LEN;
    float* __restrict__ y0 = y + (size_t)(2 * pair) * N_LEN;
    float* __restrict__ y1 = y0 + N_LEN;

    u64* sIn = sX[wid];                // slot k <-> x[c0 - 32 + k]

    // 16 packed coefficients (h[j],h[j]); pass 2 indexes reversed as h[15-j]
    u64 gph[16];
#pragma unroll
    for (int j = 0; j < 16; j++) { float hv = __ldg(h + j); gph[j] = pack2(hv, hv); }

    // ---- stage x: LDG.128 both rows, pack to u64 pairs, STS.64 (warp-private) ----
#pragma unroll
    for (int it = 0; it < 3; it++) {
        int g = lane + it * 32;        // float4 group; 72 groups of 4 pairs
        if (g < W_IN / 4) {
            int p = c0 - 32 + 4 * g;   // 16B-aligned; <0 only for the first tile
            float4 a0, a1;
            if (p >= 0) {
                a0 = *reinterpret_cast<const float4*>(x0 + p);
                a1 = *reinterpret_cast<const float4*>(x1 + p);
            } else {
                a0 = make_float4(0.f, 0.f, 0.f, 0.f);
                a1 = make_float4(0.f, 0.f, 0.f, 0.f);
            }
            int ph = sw(4 * g);        // (4g&7) in {0,4}: 4 contiguous slots in-group
            sIn[ph + 0] = pack2(a0.x, a1.x);
            sIn[ph + 1] = pack2(a0.y, a1.y);
            sIn[ph + 2] = pack2(a0.z, a1.z);
            sIn[ph + 3] = pack2(a0.w, a1.w);
        }
    }
    __syncwarp(0xffffffffu);

    const int lo = lane * EPT;
    const bool kill = (c0 == 0) && (lane < 2);      // positions 0..15 masked to 0

    // ---- pass 1: v[p] = x[p] + sum_{j=0..15} h[j]*x[p-1-j]; kept in regs ----
    u64 vbuf[EPT];
    {
        u64 r[16];                     // x ring: local pos m (-16..-1) at slot m&15
#pragma unroll
        for (int s = 0; s < 16; s++) r[s] = sIn[sw(lo + 16 + s)];   // x[c0+lo-16+s]

#pragma unroll
        for (int t = 0; t < EPT; t++) {
            u64 xi = sIn[sw(lo + 32 + t)];          // x[c0+lo+t]
            u64 acc0 = xi;
#pragma unroll
            for (int j = 0; j < 8; j++)
                acc0 = fma2(gph[j], r[(t + 15 - j) & 15], acc0);
            u64 acc1 = mul2(gph[8], r[(t + 7) & 15]);
#pragma unroll
            for (int j = 9; j < 16; j++)
                acc1 = fma2(gph[j], r[(t + 15 - j) & 15], acc1);
            vbuf[t] = add2(acc0, acc1);
            r[t & 15] = xi;
        }
    }
    if (kill) {
#pragma unroll
        for (int t = 0; t < EPT; t++) vbuf[t] = 0ULL;
    }

    // ---- tile-boundary v halo: v[c0-16+s] recomputed from x (lanes 0..15) ----
    if (lane < 16) {
        u64 v = 0ULL;
        if (c0 - 16 + lane >= 16) {                 // pos>=16 -> unmasked
            u64 xi = sIn[sw(16 + lane)];            // x[c0-16+lane]
            u64 a0 = xi;
#pragma unroll
            for (int j = 0; j < 8; j++)  a0 = fma2(gph[j], sIn[sw(15 + lane - j)], a0);
            u64 a1 = mul2(gph[8], sIn[sw(7 + lane)]);
#pragma unroll
            for (int j = 9; j < 16; j++) a1 = fma2(gph[j], sIn[sw(15 + lane - j)], a1);
            v = add2(a0, a1);
        }
        sHv[wid][lane] = v;
    }
    __syncwarp(0xffffffffu);           // sHv visible; all x reads done before y overwrites

    // ---- pass 2: y[p] = v[p] + sum_j h[15-j]*v[p-1-j]; halo via 2-level shfl ----
    {
        u64 hv[16];                    // hv[s] = v[c0+lo-16+s]
#pragma unroll
        for (int s = 0; s < 8; s++)
            hv[s] = __shfl_up_sync(0xffffffffu, vbuf[s], 2);        // lane-2's vbuf[s]
#pragma unroll
        for (int s = 8; s < 16; s++)
            hv[s] = __shfl_up_sync(0xffffffffu, vbuf[s - 8], 1);    // lane-1's vbuf[s-8]
        if (lane == 0) {
#pragma unroll
            for (int s = 0; s < 16; s++) hv[s] = sHv[wid][s];
        } else if (lane == 1) {
#pragma unroll
            for (int s = 0; s < 8; s++) hv[s] = sHv[wid][s + 8];
        }

        const int yA = 9 * lane;       // slot sw(lo+t) = 9*lane + t  (t<8)
#pragma unroll
        for (int t = 0; t < EPT; t++) {
            u64 acc0 = vbuf[t];
#pragma unroll
            for (int j = 0; j < 8; j++) {
                int k = t - 1 - j;
                u64 tap = (k >= 0) ? vbuf[k] : hv[16 + k];
                acc0 = fma2(gph[15 - j], tap, acc0);
            }
            u64 tap8;
            { int k = t - 9; tap8 = (k >= 0) ? vbuf[k] : hv[16 + k]; }
            u64 acc1 = mul2(gph[7], tap8);
#pragma unroll
            for (int j = 9; j < 16; j++) {
                int k = t - 1 - j;
                u64 tap = (k >= 0) ? vbuf[k] : hv[16 + k];
                acc1 = fma2(gph[15 - j], tap, acc1);
            }
            u64 yv = add2(acc0, acc1);
            if (kill) yv = 0ULL;       // positions 0..15 masked
            sIn[yA + t] = yv;          // stage y over dead x region
        }
    }
    __syncwarp(0xffffffffu);           // y staged

    // ---- writeout: gather u64 slots, coalesced STG.128 per row ----
#pragma unroll
    for (int it = 0; it < 2; it++) {
        int g  = lane + it * 32;       // 4-pair group, 64 groups
        int fi = 4 * g;
        int ix = 9 * (fi >> 3) + (fi & 7);          // 4 contiguous slots
        float a[4], b[4];
#pragma unroll
        for (int k = 0; k < 4; k++) unpack2(sIn[ix + k], a[k], b[k]);
        *reinterpret_cast<float4*>(y0 + c0 + fi) = make_float4(a[0], a[1], a[2], a[3]);
        *reinterpret_cast<float4*>(y1 + c0 + fi) = make_float4(b[0], b[1], b[2], b[3]);
    }
}

extern "C" void kernel_launch(void* const* d_in, const int* in_sizes, int n_in,
                              void* d_out, int out_size) {
    (void)in_sizes; (void)n_in; (void)out_size;
    const float* x = (const float*)d_in[0];
    const float* h = (const float*)d_in[1];
    float* y = (float*)d_out;

    dim3 grid(N_LEN / (NWARP * WTILE), B_ROWS / 2, 1);
    fir2<<<grid, TPB>>>(x, h, y);
}

// round 12
// speedup vs baseline: 1.2373x; 1.2373x over previous
#include <cuda_runtime.h>

// Problem constants
#define N_LEN   131072
#define B_ROWS  256

// Tiling: ONE WARP PER BLOCK; each warp owns a 512-position tile of a row-pair.
#define TPB     32
#define WTILE   512                    // positions per warp tile
#define EPT     16                     // positions per lane
#define W_IN    (WTILE + 32)           // 544 x-pairs incl 32-halo
#define PAD16(n) ((((n) + 15) / 16) * 17)
#define W_PAD   PAD16(W_IN)            // 578 u64 slots

typedef unsigned long long u64;

__device__ __forceinline__ u64 pack2(float a, float b) {
    u64 r; asm("mov.b64 %0,{%1,%2};" : "=l"(r) : "f"(a), "f"(b)); return r;
}
__device__ __forceinline__ void unpack2(u64 v, float& a, float& b) {
    asm("mov.b64 {%0,%1},%2;" : "=f"(a), "=f"(b) : "l"(v));
}
__device__ __forceinline__ u64 fma2(u64 a, u64 b, u64 c) {
    u64 d; asm("fma.rn.f32x2 %0,%1,%2,%3;" : "=l"(d) : "l"(a), "l"(b), "l"(c)); return d;
}
__device__ __forceinline__ u64 mul2(u64 a, u64 b) {
    u64 d; asm("mul.rn.f32x2 %0,%1,%2;" : "=l"(d) : "l"(a), "l"(b)); return d;
}
__device__ __forceinline__ u64 add2(u64 a, u64 b) {
    u64 d; asm("add.rn.f32x2 %0,%1,%2;" : "=l"(d) : "l"(a), "l"(b)); return d;
}

// pad-17-per-16 swizzle on u64 slots (2-way worst case for stride patterns used)
__device__ __forceinline__ int sw(int k) { return (k >> 4) * 17 + (k & 15); }

__global__ void __launch_bounds__(TPB, 16) fir2(const float* __restrict__ x,
                                                const float* __restrict__ h,
                                                float* __restrict__ y) {
    __shared__ u64 sIn[W_PAD];         // x window; reused for y staging
    __shared__ u64 sHv[16];            // tile-boundary v halo

    const int lane = threadIdx.x;
    const int pair = blockIdx.y;
    const int c0   = blockIdx.x * WTILE;               // warp tile base
    const float* __restrict__ x0 = x + (size_t)(2 * pair) * N_LEN;
    const float* __restrict__ x1 = x0 + N_LEN;
    float* __restrict__ y0 = y + (size_t)(2 * pair) * N_LEN;
    float* __restrict__ y1 = y0 + N_LEN;

    // 16 packed coefficients (h[j],h[j]); pass 2 indexes reversed as h[15-j]
    u64 gph[16];
#pragma unroll
    for (int j = 0; j < 16; j++) { float hv = __ldg(h + j); gph[j] = pack2(hv, hv); }

    // ---- stage x: LDG.128 both rows, pack to u64 pairs, STS.64 ----
#pragma unroll
    for (int it = 0; it < 5; it++) {
        int g = lane + it * 32;        // float4 group, 136 groups of 4 pairs
        if (g < W_IN / 4) {
            int p = c0 - 32 + 4 * g;   // 16B-aligned; <0 only for the first tile
            float4 a0, a1;
            if (p >= 0) {
                a0 = *reinterpret_cast<const float4*>(x0 + p);
                a1 = *reinterpret_cast<const float4*>(x1 + p);
            } else {
                a0 = make_float4(0.f, 0.f, 0.f, 0.f);
                a1 = make_float4(0.f, 0.f, 0.f, 0.f);
            }
            int ph = sw(4 * g);        // (4g&15)<=12 -> 4 contiguous slots
            sIn[ph + 0] = pack2(a0.x, a1.x);
            sIn[ph + 1] = pack2(a0.y, a1.y);
            sIn[ph + 2] = pack2(a0.z, a1.z);
            sIn[ph + 3] = pack2(a0.w, a1.w);
        }
    }
    __syncwarp(0xffffffffu);

    const int lo = lane * EPT;
    const bool kill = (c0 == 0) && (lane == 0);        // positions 0..15 masked to 0

    // ---- pass 1: v[p] = x[p] + sum_{j=0..15} h[j]*x[p-1-j]; kept in regs ----
    u64 vbuf[16];
    {
        u64 r[16];                     // x ring: local pos q at slot q&15
#pragma unroll
        for (int s = 0; s < 16; s++) r[s] = sIn[sw(lo + 16 + s)];   // x[c0+lo-16+s]

#pragma unroll
        for (int t = 0; t < EPT; t++) {
            u64 xi = sIn[sw(lo + 32 + t)];             // x[c0+lo+t]
            u64 acc0 = xi;
#pragma unroll
            for (int j = 0; j < 8; j++)
                acc0 = fma2(gph[j], r[(t + 15 - j) & 15], acc0);
            u64 acc1 = mul2(gph[8], r[(t + 7) & 15]);
#pragma unroll
            for (int j = 9; j < 16; j++)
                acc1 = fma2(gph[j], r[(t + 15 - j) & 15], acc1);
            vbuf[t] = add2(acc0, acc1);
            r[t & 15] = xi;
        }
    }
    if (kill) {
#pragma unroll
        for (int t = 0; t < EPT; t++) vbuf[t] = 0ULL;
    }

    // ---- tile-boundary v halo: v[c0-16+s] recomputed from x (lanes 0..15) ----
    if (lane < 16) {
        u64 v = 0ULL;
        if (c0 - 16 + lane >= 16) {                    // pos>=16 -> unmasked
            u64 xi = sIn[sw(16 + lane)];               // x[c0-16+lane]
            u64 a0 = xi;
#pragma unroll
            for (int j = 0; j < 8; j++)  a0 = fma2(gph[j], sIn[sw(15 + lane - j)], a0);
            u64 a1 = mul2(gph[8], sIn[sw(7 + lane)]);
#pragma unroll
            for (int j = 9; j < 16; j++) a1 = fma2(gph[j], sIn[sw(15 + lane - j)], a1);
            v = add2(a0, a1);
        }
        sHv[lane] = v;
    }
    __syncwarp(0xffffffffu);           // sHv visible; all x reads done before y overwrites

    // ---- pass 2: y[p] = v[p] + sum_j h[15-j]*v[p-1-j]; halo via shfl ----
    {
        u64 hv[16];                    // v[lo-16+s]: previous lane's vbuf
#pragma unroll
        for (int s = 0; s < 16; s++)
            hv[s] = __shfl_up_sync(0xffffffffu, vbuf[s], 1);
        if (lane == 0) {
#pragma unroll
            for (int s = 0; s < 16; s++) hv[s] = sHv[s];
        }

        const int yA = 17 * lane;      // slot sw(lo+t) = 17*lane + t
#pragma unroll
        for (int t = 0; t < EPT; t++) {
            u64 acc0 = vbuf[t];
#pragma unroll
            for (int j = 0; j < 8; j++) {
                int k = t - 1 - j;
                u64 tap = (k >= 0) ? vbuf[k] : hv[16 + k];
                acc0 = fma2(gph[15 - j], tap, acc0);
            }
            u64 tap8;
            { int k = t - 9; tap8 = (k >= 0) ? vbuf[k] : hv[16 + k]; }
            u64 acc1 = mul2(gph[7], tap8);
#pragma unroll
            for (int j = 9; j < 16; j++) {
                int k = t - 1 - j;
                u64 tap = (k >= 0) ? vbuf[k] : hv[16 + k];
                acc1 = fma2(gph[15 - j], tap, acc1);
            }
            u64 yv = add2(acc0, acc1);
            if (kill) yv = 0ULL;       // positions 0..15 masked
            sIn[yA + t] = yv;          // stage y over dead x region
        }
    }
    __syncwarp(0xffffffffu);           // y staged

    // ---- writeout: gather u64 slots, coalesced STG.128 per row ----
#pragma unroll
    for (int it = 0; it < 4; it++) {
        int g  = lane + it * 32;       // 4-pair group, 128 groups
        int fi = 4 * g;
        int ix = 17 * (fi >> 4) + (fi & 15);           // contiguous 4 slots
        float a[4], b[4];
#pragma unroll
        for (int k = 0; k < 4; k++) unpack2(sIn[ix + k], a[k], b[k]);
        *reinterpret_cast<float4*>(y0 + c0 + fi) = make_float4(a[0], a[1], a[2], a[3]);
        *reinterpret_cast<float4*>(y1 + c0 + fi) = make_float4(b[0], b[1], b[2], b[3]);
    }
}

extern "C" void kernel_launch(void* const* d_in, const int* in_sizes, int n_in,
                              void* d_out, int out_size) {
    (void)in_sizes; (void)n_in; (void)out_size;
    const float* x = (const float*)d_in[0];
    const float* h = (const float*)d_in[1];
    float* y = (float*)d_out;

    dim3 grid(N_LEN / WTILE, B_ROWS / 2, 1);
    fir2<<<grid, TPB>>>(x, h, y);
}